// round 1
// baseline (speedup 1.0000x reference)
#include <cuda_runtime.h>
#include <math.h>

#define B_ 8192
#define D_ 512
#define C_ 1000
#define K_ 8
#define EPSV 1e-8f
#define TEMPV 0.2f
#define NEGV -10000.0f

// Scratch (allowed: __device__ globals, no runtime allocation)
__device__ float g_h[(size_t)K_ * B_ * D_];          // [k][b][d]   134 MB
__device__ float g_logits[(size_t)B_ * K_ * C_];     // [b][k][c]   262 MB

// ---------------------------------------------------------------------------
// Tiled fp32 GEMM: Cout[m, n] = act( sum_k A[m,k] * W[k,n] + bias[n] )
// Block tile 128x64, BK=16, thread tile 8x4, 256 threads.
// Batched over blockIdx.z with independent strides.
// ---------------------------------------------------------------------------
template <bool RELU>
__global__ void __launch_bounds__(256) gemm_kernel(
    const float* __restrict__ A, long long aBatchStride, int ldA,
    const float* __restrict__ W, long long wBatchStride, int ldW,
    const float* __restrict__ bias, long long biasBatchStride,
    float* __restrict__ Cout, long long cBatchOff, int ldC,
    int M, int N, int Kd)
{
    constexpr int BM = 128, BN = 64, BK = 16;

    __shared__ float As[BK][BM];      // stored transposed: [k][m]
    __shared__ float Bs[BK][BN];

    const int bz = blockIdx.z;
    const float* Ab = A + (size_t)bz * aBatchStride;
    const float* Wb = W + (size_t)bz * wBatchStride;
    const float* biasb = bias + (size_t)bz * biasBatchStride;
    float* Cb = Cout + (size_t)bz * cBatchOff;

    const int n0 = blockIdx.x * BN;
    const int m0 = blockIdx.y * BM;
    const int tid = threadIdx.x;
    const int tx = tid & 15;          // 0..15 (N direction)
    const int ty = tid >> 4;          // 0..15 (M direction)

    // A-load mapping: 128 rows x 4 float4-cols, 256 threads -> 2 float4 each
    const int arow = tid & 127;       // 0..127
    const int akc  = tid >> 7;        // 0..1 (and +2)
    // B-load mapping: 16 rows x 16 float4-cols -> 1 float4 each
    const int brow = tid >> 4;        // 0..15
    const int bcol = (tid & 15) * 4;  // 0..60

    float acc[8][4];
#pragma unroll
    for (int i = 0; i < 8; i++)
#pragma unroll
        for (int j = 0; j < 4; j++) acc[i][j] = 0.0f;

    for (int kk = 0; kk < Kd; kk += BK) {
        // --- load A tile (transposed into smem) ---
#pragma unroll
        for (int r = 0; r < 2; r++) {
            int kc = (akc + 2 * r) * 4;  // 0,4,8,12
            float4 v = *(const float4*)(Ab + (size_t)(m0 + arow) * ldA + kk + kc);
            As[kc + 0][arow] = v.x;
            As[kc + 1][arow] = v.y;
            As[kc + 2][arow] = v.z;
            As[kc + 3][arow] = v.w;
        }
        // --- load B tile ---
        {
            int col = n0 + bcol;
            float4 v = make_float4(0.f, 0.f, 0.f, 0.f);
            if (col < N)  // N is a multiple of 4, so a float4 is fully in or out
                v = *(const float4*)(Wb + (size_t)(kk + brow) * ldW + col);
            *(float4*)(&Bs[brow][bcol]) = v;
        }
        __syncthreads();

#pragma unroll
        for (int k = 0; k < BK; k++) {
            float a[8], b[4];
            float4 a0 = *(const float4*)(&As[k][ty * 8]);
            float4 a1 = *(const float4*)(&As[k][ty * 8 + 4]);
            a[0] = a0.x; a[1] = a0.y; a[2] = a0.z; a[3] = a0.w;
            a[4] = a1.x; a[5] = a1.y; a[6] = a1.z; a[7] = a1.w;
            float4 bv = *(const float4*)(&Bs[k][tx * 4]);
            b[0] = bv.x; b[1] = bv.y; b[2] = bv.z; b[3] = bv.w;
#pragma unroll
            for (int i = 0; i < 8; i++)
#pragma unroll
                for (int j = 0; j < 4; j++)
                    acc[i][j] = fmaf(a[i], b[j], acc[i][j]);
        }
        __syncthreads();
    }

    // --- epilogue ---
#pragma unroll
    for (int j = 0; j < 4; j++) {
        int col = n0 + tx * 4 + j;
        if (col < N) {
            float bv = biasb[col];
#pragma unroll
            for (int i = 0; i < 8; i++) {
                float v = acc[i][j] + bv;
                if (RELU) v = fmaxf(v, 0.0f);
                Cb[(size_t)(m0 + ty * 8 + i) * ldC + col] = v;
            }
        }
    }
}

// ---------------------------------------------------------------------------
// Gating kernel: one block per batch row.
// Computes per-expert softmax stats, the probs Gram matrix, the greedy
// diversity selection (exact replication of the jax loop incl. first-index
// argmax tie-break), gate softmax, and the gated logit combine.
// Dynamic smem: 8000 logits + 8000 exps = 64000 bytes.
// ---------------------------------------------------------------------------
__global__ void __launch_bounds__(256) gating_kernel(
    const int* __restrict__ n_exp,
    float* __restrict__ out_logits,
    float* __restrict__ out_gates)
{
    extern __shared__ float sm[];
    float* sl = sm;                 // [K_ * C_] raw logits
    float* se = sm + K_ * C_;       // [K_ * C_] exp(l - max)

    __shared__ float sZ[K_];
    __shared__ float sG[K_ * K_];
    __shared__ float sgate[K_];

    const int b = blockIdx.x;
    const int tid = threadIdx.x;
    const int w = tid >> 5, lane = tid & 31;

    const float* lrow = g_logits + (size_t)b * K_ * C_;
    for (int i = tid; i < K_ * C_; i += 256) sl[i] = lrow[i];
    __syncthreads();

    // per-expert max and Z (one warp per expert; 256 threads = 8 warps = K_)
    {
        float m = -INFINITY;
        for (int c = lane; c < C_; c += 32) m = fmaxf(m, sl[w * C_ + c]);
#pragma unroll
        for (int o = 16; o > 0; o >>= 1) m = fmaxf(m, __shfl_xor_sync(0xffffffffu, m, o));
        float z = 0.0f;
        for (int c = lane; c < C_; c += 32) {
            float e = __expf(sl[w * C_ + c] - m);
            se[w * C_ + c] = e;
            z += e;
        }
#pragma unroll
        for (int o = 16; o > 0; o >>= 1) z += __shfl_xor_sync(0xffffffffu, z, o);
        if (lane == 0) sZ[w] = z;
    }
    __syncthreads();

    // Gram of softmax probs: G[i][j] = (sum_c e_i e_j) / (Z_i Z_j); 36 pairs
    for (int p = w; p < 36; p += 8) {
        int i = 0, q = p;
        while (q >= K_ - i) { q -= (K_ - i); i++; }
        int j = i + q;
        float s = 0.0f;
        for (int c = lane; c < C_; c += 32) s += se[i * C_ + c] * se[j * C_ + c];
#pragma unroll
        for (int o = 16; o > 0; o >>= 1) s += __shfl_xor_sync(0xffffffffu, s, o);
        if (lane == 0) {
            float g = s / (sZ[i] * sZ[j]);
            sG[i * K_ + j] = g;
            sG[j * K_ + i] = g;
        }
    }
    __syncthreads();

    // Serial selection on thread 0 (K=8, trivial)
    if (tid == 0) {
        float Smat[K_][K_], conf[K_], nrm[K_];
#pragma unroll
        for (int i = 0; i < K_; i++) {
            nrm[i] = sqrtf(sG[i * K_ + i]) + EPSV;
            conf[i] = 1.0f / sZ[i];  // max prob = exp(lmax-lmax)/Z
        }
#pragma unroll
        for (int i = 0; i < K_; i++)
#pragma unroll
            for (int j = 0; j < K_; j++)
                Smat[i][j] = sG[i * K_ + j] / (nrm[i] * nrm[j]);

        // argmax conf (first-index on ties, matching jnp.argmax)
        int bi = 0; float bv = conf[0];
#pragma unroll
        for (int i = 1; i < K_; i++) if (conf[i] > bv) { bv = conf[i]; bi = i; }
        bool sel[K_];
#pragma unroll
        for (int i = 0; i < K_; i++) sel[i] = false;
        sel[bi] = true;

        int n = n_exp[b];
        for (int t = 1; t < K_; t++) {
            float dist[K_];
#pragma unroll
            for (int i = 0; i < K_; i++) {
                if (sel[i]) { dist[i] = -INFINITY; }
                else {
                    float ms = -INFINITY;
#pragma unroll
                    for (int j = 0; j < K_; j++)
                        if (sel[j]) ms = fmaxf(ms, Smat[i][j]);
                    dist[i] = 1.0f - ms;
                }
            }
            int ai = 0; float av = dist[0];
#pragma unroll
            for (int i = 1; i < K_; i++) if (dist[i] > av) { av = dist[i]; ai = i; }
            if (t < n) sel[ai] = true;
        }

        float gl[K_], gm = -INFINITY;
#pragma unroll
        for (int i = 0; i < K_; i++) {
            gl[i] = (sel[i] ? conf[i] : NEGV) / TEMPV;
            gm = fmaxf(gm, gl[i]);
        }
        float gs = 0.0f;
#pragma unroll
        for (int i = 0; i < K_; i++) { gl[i] = __expf(gl[i] - gm); gs += gl[i]; }
#pragma unroll
        for (int i = 0; i < K_; i++) sgate[i] = gl[i] / gs;
    }
    __syncthreads();

    // gated combine of raw logits
    for (int c = tid; c < C_; c += 256) {
        float v = 0.0f;
#pragma unroll
        for (int k = 0; k < K_; k++) v += sgate[k] * sl[k * C_ + c];
        out_logits[(size_t)b * C_ + c] = v;
    }
    if (tid < K_) out_gates[(size_t)b * K_ + tid] = sgate[tid];
}

// ---------------------------------------------------------------------------
extern "C" void kernel_launch(void* const* d_in, const int* in_sizes, int n_in,
                              void* d_out, int out_size)
{
    const float* z    = (const float*)d_in[0];
    const int*   nexp = (const int*)d_in[1];
    const float* W1   = (const float*)d_in[2];
    const float* b1   = (const float*)d_in[3];
    const float* W2   = (const float*)d_in[4];
    const float* b2   = (const float*)d_in[5];
    float* out = (float*)d_out;

    float* hbuf = nullptr;
    float* lbuf = nullptr;
    cudaGetSymbolAddress((void**)&hbuf, g_h);
    cudaGetSymbolAddress((void**)&lbuf, g_logits);

    dim3 blk(256);

    // GEMM1: h[k][b][:] = relu(z[b] @ W1[k] + b1[k])   (M=B, N=D, Kd=D)
    dim3 g1(D_ / 64, B_ / 128, K_);
    gemm_kernel<true><<<g1, blk>>>(
        z, 0LL, D_,
        W1, (long long)D_ * D_, D_,
        b1, (long long)D_,
        hbuf, (long long)B_ * D_, D_,
        B_, D_, D_);

    // GEMM2: logits[b][k][:] = h[k][b] @ W2[k] + b2[k]  (M=B, N=C, Kd=D)
    dim3 g2((C_ + 63) / 64, B_ / 128, K_);
    gemm_kernel<false><<<g2, blk>>>(
        hbuf, (long long)B_ * D_, D_,
        W2, (long long)D_ * C_, C_,
        b2, (long long)C_,
        lbuf, (long long)C_, K_ * C_,
        B_, C_, D_);

    // Gating + combine
    cudaFuncSetAttribute(gating_kernel,
                         cudaFuncAttributeMaxDynamicSharedMemorySize, 65536);
    gating_kernel<<<B_, 256, 2 * K_ * C_ * sizeof(float)>>>(
        nexp, out, out + (size_t)B_ * C_);
}